// round 2
// baseline (speedup 1.0000x reference)
#include <cuda_runtime.h>
#include <cstdint>

#define NN 100000
#define EE 1600000
#define IN_DIM 128
#define OUT_DIM 64
#define TT 8
#define EPS_ 1e-7f

// ---------------- scratch (no allocations allowed) ----------------
__device__ int   g_cnt[NN];                       // real in-degree
__device__ int   g_off[NN];                       // CSR offsets
__device__ int   g_cur[NN];                       // fill cursors
__device__ int   g_csr[EE];                       // src node per dst-bucket slot
__device__ float g_dinv[NN];                      // 1/sqrt(deg+1)
__device__ float g_hs[(size_t)NN * OUT_DIM];      // dinv[n] * (x @ W)[n]

// ---------------- helpers ----------------
__device__ __forceinline__ float warp_sum(float v) {
#pragma unroll
    for (int o = 16; o > 0; o >>= 1) v += __shfl_xor_sync(0xffffffffu, v, o);
    return v;
}

// ---------------- kernels ----------------

__global__ void zero_kernel() {
    int i = blockIdx.x * blockDim.x + threadIdx.x;
    if (i < NN) g_cnt[i] = 0;
}

__global__ void hist_kernel(const int* __restrict__ dst) {
    int e = blockIdx.x * blockDim.x + threadIdx.x;
    if (e >= EE) return;
    atomicAdd(&g_cnt[dst[e]], 1);
}

// single-block scan: offsets, cursors, dinv
__global__ void scan_kernel() {
    __shared__ int part[1024];
    int tid = threadIdx.x;
    const int CH = (NN + 1023) / 1024;   // 98
    int lo = tid * CH;
    int hi = lo + CH; if (hi > NN) hi = NN;
    int s = 0;
    for (int i = lo; i < hi; i++) s += g_cnt[i];
    part[tid] = s;
    __syncthreads();
#pragma unroll
    for (int o = 1; o < 1024; o <<= 1) {
        int v = (tid >= o) ? part[tid - o] : 0;
        __syncthreads();
        part[tid] += v;
        __syncthreads();
    }
    int run = (tid > 0) ? part[tid - 1] : 0;
    for (int i = lo; i < hi; i++) {
        g_off[i] = run;
        g_cur[i] = run;
        g_dinv[i] = rsqrtf((float)(g_cnt[i] + 1));
        run += g_cnt[i];
    }
}

// h_s = dinv[n] * (x @ W): 8 nodes per warp, W pairs in smem, packed f32x2 FMA
__global__ void gemm_kernel(const float* __restrict__ x, const float* __restrict__ W) {
    __shared__ unsigned long long Ws[IN_DIM * OUT_DIM / 2];   // 32 KB, f32x2 pairs
    int tid = threadIdx.x;
    const float2* Wf2 = (const float2*)W;
    for (int i = tid; i < IN_DIM * OUT_DIM / 2; i += blockDim.x) {
        float2 w = Wf2[i];
        unsigned long long p;
        asm("mov.b64 %0, {%1, %2};" : "=l"(p) : "f"(w.x), "f"(w.y));
        Ws[i] = p;
    }
    __syncthreads();

    int warp = (blockIdx.x * blockDim.x + tid) >> 5;
    int lane = tid & 31;
    if (warp >= NN / 8) return;
    int n0 = warp * 8;

    // lane holds x[n][4*lane .. 4*lane+3] for each of 8 nodes
    float4 xr[8];
#pragma unroll
    for (int n = 0; n < 8; n++)
        xr[n] = *(const float4*)(x + (size_t)(n0 + n) * IN_DIM + 4 * lane);

    unsigned long long acc[8];
#pragma unroll
    for (int n = 0; n < 8; n++) acc[n] = 0ull;   // packed {0,0}

    for (int k0 = 0; k0 < IN_DIM; k0 += 4) {
        int src = k0 >> 2;
        // W pairs for these 4 k's, this lane's output pair (2*lane, 2*lane+1)
        unsigned long long w0 = Ws[(k0 + 0) * 32 + lane];
        unsigned long long w1 = Ws[(k0 + 1) * 32 + lane];
        unsigned long long w2 = Ws[(k0 + 2) * 32 + lane];
        unsigned long long w3 = Ws[(k0 + 3) * 32 + lane];
#pragma unroll
        for (int n = 0; n < 8; n++) {
            float a = __shfl_sync(0xffffffffu, xr[n].x, src);
            float bq = __shfl_sync(0xffffffffu, xr[n].y, src);
            float c = __shfl_sync(0xffffffffu, xr[n].z, src);
            float d = __shfl_sync(0xffffffffu, xr[n].w, src);
            unsigned long long xp;
            asm("mov.b64 %0, {%1, %1};" : "=l"(xp) : "f"(a));
            asm("fma.rn.f32x2 %0, %1, %2, %0;" : "+l"(acc[n]) : "l"(xp), "l"(w0));
            asm("mov.b64 %0, {%1, %1};" : "=l"(xp) : "f"(bq));
            asm("fma.rn.f32x2 %0, %1, %2, %0;" : "+l"(acc[n]) : "l"(xp), "l"(w1));
            asm("mov.b64 %0, {%1, %1};" : "=l"(xp) : "f"(c));
            asm("fma.rn.f32x2 %0, %1, %2, %0;" : "+l"(acc[n]) : "l"(xp), "l"(w2));
            asm("mov.b64 %0, {%1, %1};" : "=l"(xp) : "f"(d));
            asm("fma.rn.f32x2 %0, %1, %2, %0;" : "+l"(acc[n]) : "l"(xp), "l"(w3));
        }
    }

#pragma unroll
    for (int n = 0; n < 8; n++) {
        float2 v;
        asm("mov.b64 {%0, %1}, %2;" : "=f"(v.x), "=f"(v.y) : "l"(acc[n]));
        float di = g_dinv[n0 + n];
        v.x *= di; v.y *= di;
        *(float2*)(g_hs + (size_t)(n0 + n) * OUT_DIM + 2 * lane) = v;
    }
}

__global__ void bucket_kernel(const int* __restrict__ ei) {
    int e = blockIdx.x * blockDim.x + threadIdx.x;
    if (e >= EE) return;
    int s = ei[e];
    int d = ei[EE + e];
    int pos = atomicAdd(&g_cur[d], 1);
    g_csr[pos] = s;
}

// fused gather + 8-step Lorentz recurrence: one warp per node,
// lane holds components (2*lane, 2*lane+1)
__global__ void fused_kernel(const float* __restrict__ b,
                             float* __restrict__ o_out,
                             float* __restrict__ z_out) {
    int warp = (blockIdx.x * blockDim.x + threadIdx.x) >> 5;
    int lane = threadIdx.x & 31;
    if (warp >= NN) return;
    const int n = warp;
    const int c0 = 2 * lane;
    const size_t base = (size_t)n * OUT_DIM;

    int off = g_off[n];
    int m = g_cnt[n];

    // self-loop contribution
    float2 acc = *(const float2*)(g_hs + base + c0);

    int i = 0;
    for (; i + 2 <= m; i += 2) {
        int s0 = __ldg(&g_csr[off + i]);
        int s1 = __ldg(&g_csr[off + i + 1]);
        float2 h0 = *(const float2*)(g_hs + (size_t)s0 * OUT_DIM + c0);
        float2 h1 = *(const float2*)(g_hs + (size_t)s1 * OUT_DIM + c0);
        acc.x += h0.x + h1.x;
        acc.y += h0.y + h1.y;
    }
    if (i < m) {
        int s0 = __ldg(&g_csr[off + i]);
        float2 h0 = *(const float2*)(g_hs + (size_t)s0 * OUT_DIM + c0);
        acc.x += h0.x;
        acc.y += h0.y;
    }

    float di = g_dinv[n];
    float h0 = fmaf(di, acc.x, b[c0]);
    float h1 = fmaf(di, acc.y, b[c0 + 1]);

    float z0 = (lane == 0) ? 1.0f : 0.0f;   // time coordinate on lane 0
    float z1 = 0.0f;

#pragma unroll
    for (int t = 0; t < TT; t++) {
        // <z,h>_L = sum(z*h) - 2*z[0]*h[0]
        float p = z0 * h0 + z1 * h1;
        float p00 = __shfl_sync(0xffffffffu, z0 * h0, 0);
        float lz = warp_sum(p) - 2.0f * p00;

        float u0 = fmaf(lz, z0, h0);
        float u1 = fmaf(lz, z1, h1);

        float q = u0 * u0 + u1 * u1;
        float q00 = __shfl_sync(0xffffffffu, u0 * u0, 0);
        float uu = warp_sum(q) - 2.0f * q00;
        float un = sqrtf(fmaxf(uu, EPS_));

        float ch = coshf(un);
        float sh = sinhf(un) / un;
        z0 = ch * z0 + sh * u0;
        z1 = ch * z1 + sh * u1;

        float znew0 = __shfl_sync(0xffffffffu, z0, 0);
        float v = acoshf(fmaxf(znew0, 1.0f + EPS_));
        bool spike = (v >= 1.0f);
        if (spike) { z0 = (lane == 0) ? 1.0f : 0.0f; z1 = 0.0f; }

        if (lane == 0) o_out[(size_t)t * NN + n] = spike ? 1.0f : 0.0f;
        float2 zz = make_float2(z0, z1);
        *reinterpret_cast<float2*>(z_out + (size_t)t * NN * OUT_DIM + base + c0) = zz;
    }
}

// ---------------- launch ----------------
extern "C" void kernel_launch(void* const* d_in, const int* in_sizes, int n_in,
                              void* d_out, int out_size) {
    const float* x  = (const float*)d_in[0];
    const int*   ei = (const int*)d_in[1];
    const float* W  = (const float*)d_in[2];
    const float* b  = (const float*)d_in[3];

    float* o_out = (float*)d_out;              // [T, N]
    float* z_out = o_out + (size_t)TT * NN;    // [T, N, 64]

    zero_kernel<<<(NN + 255) / 256, 256>>>();
    hist_kernel<<<(EE + 255) / 256, 256>>>(ei + EE);
    scan_kernel<<<1, 1024>>>();
    gemm_kernel<<<(NN / 8 * 32 + 255) / 256, 256>>>(x, W);
    bucket_kernel<<<(EE + 255) / 256, 256>>>(ei);
    fused_kernel<<<(NN * 32 + 255) / 256, 256>>>(b, o_out, z_out);
}